// round 15
// baseline (speedup 1.0000x reference)
#include <cuda_runtime.h>

// SoftArgsortTopK: scores [B=128, R=8192] f32, ref_class [R] i32, k=32.
// Isotonic projection is identity for reg=0.01 => soft_sort == exact sort,
// up to reference quantization yk = fl(fl(w+x)-w), w=(k-j)/0.01 (replicated).
//
// Pipeline (4 barriers):
//   1. 32-bin histogram on top-5 key bits, computed ENTIRELY in registers via
//      bit-sliced ballots (no shared-memory atomics -- the 256-bin ATOMS
//      histogram was ~half the kernel time).
//   2. warp-0 cross-warp reduce + suffix scan -> coarse threshold T
//      (max bin with suffix count >= 32).
//   3. gather candidates (~190) via uniform-address atomicAdd (ptxas
//      REDUX-aggregates uniform-address atomics; cheap).
//   4. fused: all-pairs rank-select over candidates (8x-unrolled LDS) on the
//      candidate-owning threads, overlapped with the O(R) base sums
//      Sea = sum(exp(10s)), Src = sum(exp(10s)*rc) over non-candidates
//      (valid since s < y_j for all j there: exp(-10|s-y_j|) = exp(10s)*A_j).
//   5. each warp owns j = {warp, warp+16}: quantize, candidate corrections
//      min(ea*A_j, eb*B_j), combine, write yk + labels.
//
// Output: [0, B*k) = yk row-major, [B*k, 2*B*k) = soft labels.

constexpr int R_  = 8192;
constexpr int TK  = 32;       // k
constexpr int NT  = 512;      // threads per block
constexpr int IT  = R_ / NT;  // 16 items per thread
constexpr int NW  = NT / 32;  // 16 warps
constexpr int CAP = 4096;     // candidate buffer capacity

__device__ __forceinline__ unsigned fkey(float x) {
    // monotonic (ascending) unsigned key for float compare
    unsigned u = __float_as_uint(x);
    return u ^ (unsigned)(((int)u >> 31) | 0x80000000);
}

__global__ void __launch_bounds__(NT, 1)
soft_argsort_topk_kernel(const float* __restrict__ scores,
                         const int*   __restrict__ ref_class,
                         float* __restrict__ yk_out,
                         float* __restrict__ lbl_out)
{
    __shared__ int   hw[NW][33];         // per-warp 32-bin counts (padded)
    __shared__ float cx[CAP];            // candidate values
    __shared__ float crc[CAP];           // candidate ref_class (as float)
    __shared__ int   s_T, s_cnt;
    __shared__ float y_raw[TK];
    __shared__ float pSea[NW], pSrc[NW];

    const int b    = blockIdx.x;
    const int tid  = threadIdx.x;
    const int warp = tid >> 5, lane = tid & 31;
    const float* row = scores + (size_t)b * R_;

    // ---- global loads (latency overlaps the register histogram setup) ----
    float items[IT], rcf[IT];
    {
        const float4* r4 = reinterpret_cast<const float4*>(row) + tid * (IT / 4);
        const int4*   c4 = reinterpret_cast<const int4*>(ref_class) + tid * (IT / 4);
#pragma unroll
        for (int q = 0; q < IT / 4; q++) {
            float4 v = r4[q];
            int4   w = c4[q];
            items[4*q+0] = v.x; items[4*q+1] = v.y;
            items[4*q+2] = v.z; items[4*q+3] = v.w;
            rcf[4*q+0] = (float)w.x; rcf[4*q+1] = (float)w.y;
            rcf[4*q+2] = (float)w.z; rcf[4*q+3] = (float)w.w;
        }
    }

    // ---- bit-sliced ballot histogram: lane L counts items in bin L ----
    // bin = top 5 bits of key; XNOR-match per bit, popc-accumulate. No LSU.
    {
        unsigned inv0 = (lane & 1)  ? 0u : 0xffffffffu;
        unsigned inv1 = (lane & 2)  ? 0u : 0xffffffffu;
        unsigned inv2 = (lane & 4)  ? 0u : 0xffffffffu;
        unsigned inv3 = (lane & 8)  ? 0u : 0xffffffffu;
        unsigned inv4 = (lane & 16) ? 0u : 0xffffffffu;
        int cnt = 0;
#pragma unroll
        for (int i = 0; i < IT; i++) {
            unsigned cb = fkey(items[i]) >> 27;
            unsigned b0 = __ballot_sync(0xffffffffu, cb & 1u);
            unsigned b1 = __ballot_sync(0xffffffffu, cb & 2u);
            unsigned b2 = __ballot_sync(0xffffffffu, cb & 4u);
            unsigned b3 = __ballot_sync(0xffffffffu, cb & 8u);
            unsigned b4 = __ballot_sync(0xffffffffu, cb & 16u);
            unsigned m = (b0 ^ inv0) & (b1 ^ inv1) & (b2 ^ inv2)
                       & (b3 ^ inv3) & (b4 ^ inv4);
            cnt += __popc(m);
        }
        hw[warp][lane] = cnt;
    }
    if (tid == 0) s_cnt = 0;
    __syncthreads();                                         // B1

    // ---- warp 0: reduce across warps, suffix scan, pick threshold bin T ----
    if (tid < 32) {
        int s = 0;
#pragma unroll
        for (int w = 0; w < NW; w++) s += hw[w][tid];  // padded: conflict-free
        // inclusive suffix sum over lanes (lane L: count of bins >= L)
#pragma unroll
        for (int o = 1; o < 32; o <<= 1) {
            int t = __shfl_down_sync(0xffffffffu, s, o);
            if (tid < 32 - o) s += t;
        }
        // suffix is nonincreasing in lane; highest lane with suffix >= TK:
        unsigned m = __ballot_sync(0xffffffffu, s >= TK);
        if (tid == 0) s_T = 31 - __clz(m);
    }
    __syncthreads();                                         // B2

    // ---- gather candidates (uniform-address atomic: REDUX-aggregated) ----
    const unsigned T = (unsigned)s_T;
#pragma unroll
    for (int i = 0; i < IT; i++) {
        float s = items[i];
        if ((fkey(s) >> 27) >= T) {
            int p = atomicAdd(&s_cnt, 1);
            if (p < CAP) { cx[p] = s; crc[p] = rcf[i]; }
        }
    }
    __syncthreads();                                         // B3

    const int c = min(s_cnt, CAP);

    // ---- fused: rank-select (candidate-owning threads) overlapped with the
    //      O(R) exp base-sum pass (all threads) ----
    for (int t = tid; t < c; t += NT) {
        float x = cx[t];
        int rank = 0;
        int i = 0;
        // 8x unrolled: 8 independent LDS in flight per step
        for (; i + 8 <= c; i += 8) {
#pragma unroll
            for (int u = 0; u < 8; u++) {
                float xi = cx[i + u];
                rank += (xi > x) || (xi == x && (i + u) < t);
            }
        }
        for (; i < c; i++) {
            float xi = cx[i];
            rank += (xi > x) || (xi == x && i < t);
        }
        if (rank < TK) y_raw[TK - 1 - rank] = x;   // ascending positions
    }
    {
        float Sea = 0.0f, Src = 0.0f;
#pragma unroll
        for (int i = 0; i < IT; i++) {
            float s = items[i];
            if ((fkey(s) >> 27) < T) {
                float ea = __expf(10.0f * s);
                Sea += ea;
                Src  = fmaf(ea, rcf[i], Src);
            }
        }
#pragma unroll
        for (int o = 16; o; o >>= 1) {
            Sea += __shfl_xor_sync(0xffffffffu, Sea, o);
            Src += __shfl_xor_sync(0xffffffffu, Src, o);
        }
        if (lane == 0) { pSea[warp] = Sea; pSrc[warp] = Src; }
    }
    __syncthreads();                                         // B4

    // ---- each warp owns j0 = warp, j1 = warp+16: quantize + corrections ----
    {
        const int j0 = warp, j1 = warp + 16;
        // reference quantization: y = fl(fl(w + x) - w), w = (TK - j)/0.01
        float x0 = y_raw[j0], x1 = y_raw[j1];
        float w0 = __fdiv_rn((float)(TK - j0), 0.01f);
        float w1 = __fdiv_rn((float)(TK - j1), 0.01f);
        float y0 = __fsub_rn(__fadd_rn(w0, x0), w0);
        float y1 = __fsub_rn(__fadd_rn(w1, x1), w1);
        float A0 = __expf(-10.0f * y0), B0 = __expf(10.0f * y0);
        float A1 = __expf(-10.0f * y1), B1 = __expf(10.0f * y1);

        float d0 = 0.0f, n0 = 0.0f, d1 = 0.0f, n1 = 0.0f;
        for (int p = lane; p < c; p += 32) {
            float x  = cx[p], r = crc[p];
            float ea = __expf( 10.0f * x);
            float eb = __expf(-10.0f * x);
            float e0 = fminf(ea * A0, eb * B0);
            float e1 = fminf(ea * A1, eb * B1);
            d0 += e0; n0 = fmaf(e0, r, n0);
            d1 += e1; n1 = fmaf(e1, r, n1);
        }
#pragma unroll
        for (int o = 16; o; o >>= 1) {
            d0 += __shfl_xor_sync(0xffffffffu, d0, o);
            n0 += __shfl_xor_sync(0xffffffffu, n0, o);
            d1 += __shfl_xor_sync(0xffffffffu, d1, o);
            n1 += __shfl_xor_sync(0xffffffffu, n1, o);
        }
        if (lane == 0) {
            float Sea = 0.0f, Src = 0.0f;
#pragma unroll
            for (int w = 0; w < NW; w++) { Sea += pSea[w]; Src += pSrc[w]; }
            yk_out[b * TK + j0] = y0;
            yk_out[b * TK + j1] = y1;
            lbl_out[b * TK + j0] = fmaf(A0, Src, n0) / fmaf(A0, Sea, d0);
            lbl_out[b * TK + j1] = fmaf(A1, Src, n1) / fmaf(A1, Sea, d1);
        }
    }
}

extern "C" void kernel_launch(void* const* d_in, const int* in_sizes, int n_in,
                              void* d_out, int out_size)
{
    const float* scores    = (const float*)d_in[0];
    const int*   ref_class = (const int*)d_in[1];
    const int R = in_sizes[1];           // 8192
    const int B = in_sizes[0] / R;       // 128

    float* yk_out  = (float*)d_out;
    float* lbl_out = (float*)d_out + (size_t)B * TK;

    soft_argsort_topk_kernel<<<B, NT>>>(scores, ref_class, yk_out, lbl_out);
}